// round 15
// baseline (speedup 1.0000x reference)
#include <cuda_runtime.h>
#include <cstdint>

#define NC      32
#define NSTEPS  32
#define DDIM    30
#define BLOCK   256
#define MBINS   16384          // 2^14 bins
#define NT      8              // fast path: exactly 8 thetas

// Interleaved table: row `bin` = 8 x (A,B) float2 = 64B, 64B-aligned.
// A==NaN => impure (bin,theta).
__device__ __align__(64) float4 g_tab4[MBINS * 4];

// --- per-theta cell transforms (threads 0..31 of a block with blockIdx.y=t)
__device__ __forceinline__ void build_table(const float* __restrict__ theta,
                                            const float* __restrict__ basis,
                                            int t, int tid,
                                            float* s0, float* s1)
{
    if (tid < NC) {
        const float dT = 1.0f / (float)NSTEPS;
        const float* __restrict__ ba = basis + (2 * tid)     * DDIM;
        const float* __restrict__ bb = basis + (2 * tid + 1) * DDIM;
        const float* __restrict__ th = theta + t * DDIM;
        float a = 0.0f, b = 0.0f;
        #pragma unroll
        for (int j = 0; j < DDIM; ++j) {
            float tj = th[j];
            a = fmaf(ba[j], tj, a);
            b = fmaf(bb[j], tj, b);
        }
        a *= dT;
        b *= dT;
        float ea  = expf(a);
        float phi = (fabsf(a) < 1e-6f) ? (1.0f + 0.5f * a) : (expm1f(a) / a);
        s0[tid] = ea;
        s1[tid] = b * phi;
    }
}

// All-8-theta tables, layout s0[t*32+c]; needs blockDim.x >= 256.
__device__ __forceinline__ void build_tables8(const float* __restrict__ theta,
                                              const float* __restrict__ basis,
                                              int tid, float* s0, float* s1)
{
    if (tid < NT * NC) {
        const int t = tid >> 5;
        const int c = tid & 31;
        const float dT = 1.0f / (float)NSTEPS;
        const float* __restrict__ ba = basis + (2 * c)     * DDIM;
        const float* __restrict__ bb = basis + (2 * c + 1) * DDIM;
        const float* __restrict__ th = theta + t * DDIM;
        float a = 0.0f, b = 0.0f;
        #pragma unroll
        for (int j = 0; j < DDIM; ++j) {
            float tj = th[j];
            a = fmaf(ba[j], tj, a);
            b = fmaf(bb[j], tj, b);
        }
        a *= dT;
        b *= dT;
        float ea  = expf(a);
        float phi = (fabsf(a) < 1e-6f) ? (1.0f + 0.5f * a) : (expm1f(a) / a);
        s0[tid] = ea;
        s1[tid] = b * phi;
    }
}

// Magic-number cell bits; low 5 bits == cell; shfl wraps srcLane mod 32.
__device__ __forceinline__ int cell_bits(float x)
{
    int b = (int)__float_as_uint(__fmaf_rz(x, 32.0f, 8388608.0f));
    b = max(b, 0x4B000000);
    b = min(b, 0x4B00001F);
    return b;
}

// ---------------------------------------------------------------------------
// Setup: one thread per (theta, bin); dual-edge trace with SHFL table
// (all lanes active, uniform trip count); write interleaved row entry.
// ---------------------------------------------------------------------------
__global__ __launch_bounds__(BLOCK)
void setup_kernel(const float* __restrict__ theta,
                  const float* __restrict__ basis)
{
    __shared__ float s0[NC], s1[NC];
    const int t   = blockIdx.y;
    const int tid = threadIdx.x;

    build_table(theta, basis, t, tid, s0, s1);
    __syncthreads();

    const float T0 = s0[tid & 31];
    const float T1 = s1[tid & 31];

    const int bin = blockIdx.x * BLOCK + tid;
    float xl = (float)bin       * (1.0f / (float)MBINS);  // exact fp32
    float xr = (float)(bin + 1) * (1.0f / (float)MBINS);

    float A = 1.0f, B = 0.0f;
    bool pure = true;

    #pragma unroll
    for (int s = 0; s < NSTEPS; ++s) {
        int bl = cell_bits(xl);
        int br = cell_bits(xr);
        pure = pure && (bl == br);
        float t0l = __shfl_sync(0xFFFFFFFFu, T0, bl);
        float t1l = __shfl_sync(0xFFFFFFFFu, T1, bl);
        float t0r = __shfl_sync(0xFFFFFFFFu, T0, br);
        float t1r = __shfl_sync(0xFFFFFFFFu, T1, br);
        xl = fmaf(t0l, xl, t1l);
        xr = fmaf(t0r, xr, t1r);
        A  = A * t0l;
        B  = fmaf(t0l, B, t1l);
    }

    ((float2*)g_tab4)[bin * NT + t] =
        pure ? make_float2(A, B)
             : make_float2(__int_as_float(0x7FC00000), 0.0f);
}

// ---------------------------------------------------------------------------
// Main (n_theta==8): 2 points/thread, one 64B row gather serves all 8 thetas.
// ---------------------------------------------------------------------------
__global__ __launch_bounds__(BLOCK)
void main_kernel(const float* __restrict__ points,
                 const float* __restrict__ theta,
                 const float* __restrict__ basis,
                 float* __restrict__ out,
                 int n_points)
{
    __shared__ float s0[NT * NC], s1[NT * NC];
    __shared__ int   s_list[BLOCK * 2 * NT];   // expanded (idx,theta) codes
    __shared__ int   s_cnt;

    const int tid  = threadIdx.x;
    const int lane = tid & 31;

    if (tid == 0) s_cnt = 0;
    build_tables8(theta, basis, tid, s0, s1);
    __syncthreads();

    const int base = blockIdx.x * (BLOCK * 2) + tid * 2;
    const bool full = (base + 2 <= n_points);

    float x0, x1;
    if (full) {
        float2 xp = *(const float2*)(points + base);
        x0 = xp.x; x1 = xp.y;
    } else {
        x0 = (base     < n_points) ? points[base]     : 0.5f;
        x1 = (base + 1 < n_points) ? points[base + 1] : 0.5f;
    }

    // Exact bins (multiply by 2^14 is exact for x in [0,1)).
    int  v0 = (int)__fmul_rz(x0, (float)MBINS);
    int  v1 = (int)__fmul_rz(x1, (float)MBINS);
    int  b0 = min(max(v0, 0), MBINS - 1);
    int  b1 = min(max(v1, 0), MBINS - 1);
    bool oob0 = (v0 != b0), oob1 = (v1 != b1);

    // 8 independent row gathers (2 rows x 4 LDG.128), back-to-back.
    float4 r0[4], r1[4];
    #pragma unroll
    for (int j = 0; j < 4; ++j) r0[j] = __ldg(&g_tab4[b0 * 4 + j]);
    #pragma unroll
    for (int j = 0; j < 4; ++j) r1[j] = __ldg(&g_tab4[b1 * 4 + j]);

    // Apply all 8 thetas to both points; collect impure mask (bit t*2+p).
    int mask = 0;
    #pragma unroll
    for (int t = 0; t < NT; ++t) {
        float4 q0 = r0[t >> 1];
        float4 q1 = r1[t >> 1];
        float A0 = (t & 1) ? q0.z : q0.x, B0 = (t & 1) ? q0.w : q0.y;
        float A1 = (t & 1) ? q1.z : q1.x, B1 = (t & 1) ? q1.w : q1.y;
        float y0 = fmaf(A0, x0, B0);
        float y1 = fmaf(A1, x1, B1);

        float* o = out + (size_t)t * (size_t)n_points;
        if (full) {
            *(float2*)(o + base) = make_float2(y0, y1);
        } else {
            if (base     < n_points) o[base]     = y0;
            if (base + 1 < n_points) o[base + 1] = y1;
        }
        bool bad0 = ((A0 != A0) || oob0) && (base     < n_points);
        bool bad1 = ((A1 != A1) || oob1) && (base + 1 < n_points);
        if (bad0) mask |= 1 << (t * 2);
        if (bad1) mask |= 1 << (t * 2 + 1);
    }

    // Warp-aggregated compaction of (idx, theta) pairs.
    {
        int cnt = __popc((unsigned)mask);
        int scan = cnt;
        #pragma unroll
        for (int d = 1; d < 32; d <<= 1) {
            int v = __shfl_up_sync(0xFFFFFFFFu, scan, d);
            if (lane >= d) scan += v;
        }
        int wtot = __shfl_sync(0xFFFFFFFFu, scan, 31);
        if (wtot) {
            int wbase = 0;
            if (lane == 31) wbase = atomicAdd(&s_cnt, wtot);
            wbase = __shfl_sync(0xFFFFFFFFu, wbase, 31);
            int pos = wbase + scan - cnt;
            #pragma unroll
            for (int b = 0; b < 2 * NT; ++b) {
                if (mask & (1 << b)) {
                    int t   = b >> 1;
                    int idx = base + (b & 1);
                    s_list[pos++] = (idx << 3) | t;
                }
            }
        }
    }
    __syncthreads();

    // Slow path: exact reference iteration using SMEM tables (divergence-safe).
    const int n_imp = s_cnt;
    for (int e = tid; e < n_imp; e += BLOCK) {
        int code = s_list[e];
        int idx  = code >> 3;
        int t    = code & 7;
        float xx = points[idx];
        #pragma unroll
        for (int s = 0; s < NSTEPS; ++s) {
            float xc = fminf(fmaxf(xx * (float)NC, 0.0f), (float)(NC - 1));
            int c = (int)xc;
            xx = fmaf(s0[t * 32 + c], xx, s1[t * 32 + c]);
        }
        out[(size_t)t * (size_t)n_points + idx] = xx;
    }
}

// ---------------------------------------------------------------------------
// Generic fallback (n_theta != 8): proven R8 iterative kernel.
// ---------------------------------------------------------------------------
__global__ __launch_bounds__(BLOCK)
void generic_kernel(const float* __restrict__ points,
                    const float* __restrict__ theta,
                    const float* __restrict__ basis,
                    float* __restrict__ out,
                    int n_points)
{
    __shared__ float s0[NC], s1[NC];
    const int t    = blockIdx.y;
    const int tid  = threadIdx.x;
    const int lane = tid & 31;

    build_table(theta, basis, t, tid, s0, s1);
    __syncthreads();

    const float T0 = s0[lane];
    const float T1 = s1[lane];

    const int base = blockIdx.x * (BLOCK * 8) + tid;
    float x[8];
    #pragma unroll
    for (int k = 0; k < 8; ++k) {
        int idx = base + k * BLOCK;
        x[k] = (idx < n_points) ? points[idx] : 0.0f;
    }
    #pragma unroll 4
    for (int s = 0; s < NSTEPS; ++s) {
        #pragma unroll
        for (int k = 0; k < 8; ++k) {
            int bi = cell_bits(x[k]);
            float t0 = __shfl_sync(0xFFFFFFFFu, T0, bi);
            float t1 = __shfl_sync(0xFFFFFFFFu, T1, bi);
            x[k] = fmaf(t0, x[k], t1);
        }
    }
    float* __restrict__ o = out + (size_t)t * (size_t)n_points;
    #pragma unroll
    for (int k = 0; k < 8; ++k) {
        int idx = base + k * BLOCK;
        if (idx < n_points) o[idx] = x[k];
    }
}

extern "C" void kernel_launch(void* const* d_in, const int* in_sizes, int n_in,
                              void* d_out, int out_size)
{
    const float* points = (const float*)d_in[0];  // [1, n_points]
    const float* theta  = (const float*)d_in[1];  // [n_theta, 30]
    const float* basis  = (const float*)d_in[2];  // [64, 30]
    float* out = (float*)d_out;                   // [n_theta, 1, n_points]

    const int n_points = in_sizes[0];
    const int n_theta  = in_sizes[1] / DDIM;

    if (n_theta == NT) {
        dim3 sgrid(MBINS / BLOCK, NT);
        setup_kernel<<<sgrid, BLOCK>>>(theta, basis);
        int mblocks = (n_points + BLOCK * 2 - 1) / (BLOCK * 2);
        main_kernel<<<mblocks, BLOCK>>>(points, theta, basis, out, n_points);
    } else {
        dim3 grid((n_points + BLOCK * 8 - 1) / (BLOCK * 8), n_theta);
        generic_kernel<<<grid, BLOCK>>>(points, theta, basis, out, n_points);
    }
}